// round 10
// baseline (speedup 1.0000x reference)
#include <cuda_runtime.h>
#include <cuda_bf16.h>
#include <cstdint>
#include <math.h>

// Problem shape (fixed by setup_inputs)
#define Bn 2048
#define Kn 256
#define Dn 512

#define NCTA 128        // persistent grid; must all be co-resident (<= #SMs)

// bf16 staging buffers (__device__ globals: allocation-free)
__device__ __nv_bfloat16 g_abig[Bn * 1024];  // [b][ 0..511: x^2 | 512..1023: x ]
__device__ __nv_bfloat16 g_bmat[Kn * 1024];  // [k][ 0..511: bw | 512..1023: -2*bw*c ]
__device__ __nv_bfloat16 g_rbf [Bn * Kn];    // rbf result, K-major for phase 2
__device__ __nv_bfloat16 g_wt  [Dn * Kn];    // softplus(W) transposed: [d][k]
__device__ float         g_ck  [Kn];         // sum_d bw*c^2

// software grid barrier state (zero-init; self-resets at kernel end)
__device__ unsigned g_count;
__device__ unsigned g_done;

// ---------------------------------------------------------------------------
// Helpers (arch-generic: ldmatrix / mma.sync / cp.async — NO tcgen05, the
// harness PTX stage targets plain compute_103)
// ---------------------------------------------------------------------------
__device__ __forceinline__ uint32_t s2u(const void* p) {
    uint32_t a;
    asm("{ .reg .u64 t; cvta.to.shared.u64 t, %1; cvt.u32.u64 %0, t; }"
        : "=r"(a) : "l"(p));
    return a;
}
#define SW128(o) ((o) ^ (((o) >> 3) & 0x70))

__device__ __forceinline__ void cp16(uint32_t s, const void* g) {
    asm volatile("cp.async.cg.shared.global [%0], [%1], 16;" :: "r"(s), "l"(g));
}

__device__ __forceinline__ void ldsm4(uint32_t* r, uint32_t addr) {
    asm volatile("ldmatrix.sync.aligned.m8n8.x4.shared.b16 {%0,%1,%2,%3}, [%4];"
                 : "=r"(r[0]), "=r"(r[1]), "=r"(r[2]), "=r"(r[3]) : "r"(addr));
}

__device__ __forceinline__ void mma16816(float* c, const uint32_t* a, const uint32_t* b) {
    asm volatile(
        "mma.sync.aligned.m16n8k16.row.col.f32.bf16.bf16.f32 "
        "{%0,%1,%2,%3}, {%4,%5,%6,%7}, {%8,%9}, {%0,%1,%2,%3};"
        : "+f"(c[0]), "+f"(c[1]), "+f"(c[2]), "+f"(c[3])
        : "r"(a[0]), "r"(a[1]), "r"(a[2]), "r"(a[3]), "r"(b[0]), "r"(b[1]));
}

__device__ __forceinline__ uint32_t bits2(__nv_bfloat162 v) {
    return *(uint32_t*)&v;
}

// Grid barrier: all NCTA CTAs arrive, then proceed. Counter monotone within
// one kernel run; reset at kernel end so graph replays see fresh state.
__device__ __forceinline__ void gridbar(unsigned target) {
    __threadfence();
    __syncthreads();
    if (threadIdx.x == 0) {
        atomicAdd(&g_count, 1u);
        while (atomicAdd(&g_count, 0u) < target) { }
    }
    __syncthreads();
    __threadfence();
}

// ---------------------------------------------------------------------------
// GEMM tile body (identical math to R8 known-good kernels), split-K across
// two warp groups, 6-stage cp.async pipeline in 96KB dynamic smem.
// ---------------------------------------------------------------------------
#define STAGE_BYTES 16384
#define NSTAGE 6
#define SMEMSZ (NSTAGE * STAGE_BYTES)   // 98304

template<int LD>
__device__ __forceinline__ void load_chunk(uint32_t T0, const __nv_bfloat16* A,
                                           const __nv_bfloat16* Bm,
                                           int m0, int n0, int ch, int tid) {
    uint32_t sa = T0 + (ch % NSTAGE) * STAGE_BYTES;
    const __nv_bfloat16* ga = A  + (size_t)m0 * LD + ch * 64;
    const __nv_bfloat16* gb = Bm + (size_t)n0 * LD + ch * 64;
    #pragma unroll
    for (int q = 0; q < 2; q++) {
        int u = tid + q * 256;
        int r = u >> 3, cc = u & 7;
        uint32_t off = SW128((uint32_t)(r * 128 + cc * 16));
        cp16(sa        + off, ga + (size_t)r * LD + cc * 8);
        cp16(sa + 8192 + off, gb + (size_t)r * LD + cc * 8);
    }
}

template<bool ISG2>
__device__ __forceinline__ void gemm_tile(char* sm, int m0, int n0,
                                          float* __restrict__ out) {
    constexpr int LD     = ISG2 ? 256 : 1024;
    constexpr int NCHUNK = ISG2 ? 4   : 16;
    constexpr int NSTEP  = NCHUNK / 2;
    const __nv_bfloat16* A  = ISG2 ? g_rbf : g_abig;
    const __nv_bfloat16* Bm = ISG2 ? g_wt  : g_bmat;

    const uint32_t T0 = s2u(sm);
    const int tid = threadIdx.x, wid = tid >> 5, l = tid & 31;
    const int grp = wid >> 2, wg = wid & 3;
    const int wm = wg & 1, wn = wg >> 1;

    const int lr = l & 7, sel = l >> 3;
    const int a_row = wm * 32 + (sel & 1) * 8 + lr;
    const uint32_t a_kb = (uint32_t)((sel >> 1) * 16);
    const int b_row = wn * 32 + (sel >> 1) * 8 + lr;
    const uint32_t b_kb = (uint32_t)((sel & 1) * 16);

    __syncthreads();   // protect smem reuse from any previous tile/phase

    float acc[2][4][4];
    #pragma unroll
    for (int mi = 0; mi < 2; mi++)
        #pragma unroll
        for (int nj = 0; nj < 4; nj++)
            #pragma unroll
            for (int e = 0; e < 4; e++) acc[mi][nj][e] = 0.0f;

    load_chunk<LD>(T0, A, Bm, m0, n0, 0, tid);
    load_chunk<LD>(T0, A, Bm, m0, n0, 1, tid);
    asm volatile("cp.async.commit_group;");
    if (NSTEP > 1) {
        load_chunk<LD>(T0, A, Bm, m0, n0, 2, tid);
        load_chunk<LD>(T0, A, Bm, m0, n0, 3, tid);
        asm volatile("cp.async.commit_group;");
    }

    for (int t = 0; t < NSTEP; t++) {
        if (t < NSTEP - 1) asm volatile("cp.async.wait_group 1;");
        else               asm volatile("cp.async.wait_group 0;");
        __syncthreads();
        if (t + 2 < NSTEP) {
            load_chunk<LD>(T0, A, Bm, m0, n0, 2 * t + 4, tid);
            load_chunk<LD>(T0, A, Bm, m0, n0, 2 * t + 5, tid);
            asm volatile("cp.async.commit_group;");
        }

        const int ch = 2 * t + grp;
        const uint32_t sa  = T0 + (ch % NSTAGE) * STAGE_BYTES;
        const uint32_t sbb = sa + 8192;
        #pragma unroll
        for (int ks = 0; ks < 4; ks++) {
            uint32_t a[2][4], b[2][4];
            #pragma unroll
            for (int mi = 0; mi < 2; mi++)
                ldsm4(a[mi], sa + SW128((uint32_t)((a_row + mi * 16) * 128)
                                        + (uint32_t)(ks * 32) + a_kb));
            #pragma unroll
            for (int bi = 0; bi < 2; bi++)
                ldsm4(b[bi], sbb + SW128((uint32_t)((b_row + bi * 16) * 128)
                                         + (uint32_t)(ks * 32) + b_kb));
            #pragma unroll
            for (int mi = 0; mi < 2; mi++)
                #pragma unroll
                for (int nj = 0; nj < 4; nj++)
                    mma16816(acc[mi][nj], a[mi], &b[nj >> 1][(nj & 1) * 2]);
        }
    }

    // ---- cross-group reduce through smem (pitch 72 floats) ---------------
    float* Rb = (float*)sm;
    const int rrow = wm * 32 + (l >> 2);
    const int rcol = wn * 32 + 2 * (l & 3);
    __syncthreads();
    if (grp == 1) {
        #pragma unroll
        for (int mi = 0; mi < 2; mi++)
            #pragma unroll
            for (int nj = 0; nj < 4; nj++) {
                const int r = rrow + mi * 16, c = rcol + nj * 8;
                *(float2*)&Rb[r * 72 + c]       = make_float2(acc[mi][nj][0], acc[mi][nj][1]);
                *(float2*)&Rb[(r + 8) * 72 + c] = make_float2(acc[mi][nj][2], acc[mi][nj][3]);
            }
    }
    __syncthreads();
    if (grp == 0) {
        #pragma unroll
        for (int mi = 0; mi < 2; mi++)
            #pragma unroll
            for (int nj = 0; nj < 4; nj++) {
                const int r = rrow + mi * 16, c = rcol + nj * 8;
                float2 p0 = *(const float2*)&Rb[r * 72 + c];
                float2 p1 = *(const float2*)&Rb[(r + 8) * 72 + c];
                acc[mi][nj][0] += p0.x;  acc[mi][nj][1] += p0.y;
                acc[mi][nj][2] += p1.x;  acc[mi][nj][3] += p1.y;
            }

        const int erow = m0 + rrow;
        if (!ISG2) {
            #pragma unroll
            for (int mi = 0; mi < 2; mi++) {
                #pragma unroll
                for (int nj = 0; nj < 4; nj++) {
                    const int col = rcol + nj * 8;
                    const float ck0 = g_ck[n0 + col];
                    const float ck1 = g_ck[n0 + col + 1];
                    const int r = erow + mi * 16;
                    float v0 = __expf(-0.5f * (acc[mi][nj][0] + ck0));
                    float v1 = __expf(-0.5f * (acc[mi][nj][1] + ck1));
                    float v2 = __expf(-0.5f * (acc[mi][nj][2] + ck0));
                    float v3 = __expf(-0.5f * (acc[mi][nj][3] + ck1));
                    __nv_bfloat162 p0 = __floats2bfloat162_rn(v0, v1);
                    __nv_bfloat162 p1 = __floats2bfloat162_rn(v2, v3);
                    *(__nv_bfloat162*)&g_rbf[(size_t)r * Kn + n0 + col]       = p0;
                    *(__nv_bfloat162*)&g_rbf[(size_t)(r + 8) * Kn + n0 + col] = p1;
                }
            }
        } else {
            const float eps = 1e-3f;
            #pragma unroll
            for (int mi = 0; mi < 2; mi++) {
                #pragma unroll
                for (int nj = 0; nj < 4; nj++) {
                    const int col = n0 + rcol + nj * 8;
                    const int r = erow + mi * 16;
                    float2 o0, o1;
                    o0.x = __fdividef(1.0f, acc[mi][nj][0] + eps);
                    o0.y = __fdividef(1.0f, acc[mi][nj][1] + eps);
                    o1.x = __fdividef(1.0f, acc[mi][nj][2] + eps);
                    o1.y = __fdividef(1.0f, acc[mi][nj][3] + eps);
                    *(float2*)(out + (size_t)r * Dn + col)       = o0;
                    *(float2*)(out + (size_t)(r + 8) * Dn + col) = o1;
                }
            }
        }
    }
    __syncthreads();   // everyone done with Rb before smem reused
}

// ---------------------------------------------------------------------------
// Persistent megakernel: prep -> gridbar -> G1 -> gridbar -> G2 x2.
// 128 CTAs x 256 threads, 96KB dynamic smem (all co-resident => barrier safe).
// ---------------------------------------------------------------------------
__global__ void __launch_bounds__(256, 1)
mega_kern(const float* __restrict__ x, const float* __restrict__ centers,
          const float* __restrict__ bandwidths, const float* __restrict__ raw,
          float* __restrict__ out) {
    extern __shared__ char sm[];
    const int c = blockIdx.x, tid = threadIdx.x;

    // ================= Phase 0: prep =================
    // prepA: 512 units of (256 thr x 16 elems); CTA c does units 2c, 2c+1... 
    // (2 units per CTA covers 256 units; Bn*Dn elems = 1024*1024 = 256*256*16)
    #pragma unroll
    for (int uu = 0; uu < 2; uu++) {
        const int e = ((c * 2 + uu) * 256 + tid) * 16;
        const int row = e >> 9;
        const int d = e & 511;
        const float4* src = (const float4*)(x + e);
        float4 v0 = src[0], v1 = src[1], v2 = src[2], v3 = src[3];
        uint4 sq0, sq1, xx0, xx1;
        sq0.x = bits2(__floats2bfloat162_rn(v0.x * v0.x, v0.y * v0.y));
        sq0.y = bits2(__floats2bfloat162_rn(v0.z * v0.z, v0.w * v0.w));
        sq0.z = bits2(__floats2bfloat162_rn(v1.x * v1.x, v1.y * v1.y));
        sq0.w = bits2(__floats2bfloat162_rn(v1.z * v1.z, v1.w * v1.w));
        sq1.x = bits2(__floats2bfloat162_rn(v2.x * v2.x, v2.y * v2.y));
        sq1.y = bits2(__floats2bfloat162_rn(v2.z * v2.z, v2.w * v2.w));
        sq1.z = bits2(__floats2bfloat162_rn(v3.x * v3.x, v3.y * v3.y));
        sq1.w = bits2(__floats2bfloat162_rn(v3.z * v3.z, v3.w * v3.w));
        xx0.x = bits2(__floats2bfloat162_rn(v0.x, v0.y));
        xx0.y = bits2(__floats2bfloat162_rn(v0.z, v0.w));
        xx0.z = bits2(__floats2bfloat162_rn(v1.x, v1.y));
        xx0.w = bits2(__floats2bfloat162_rn(v1.z, v1.w));
        xx1.x = bits2(__floats2bfloat162_rn(v2.x, v2.y));
        xx1.y = bits2(__floats2bfloat162_rn(v2.z, v2.w));
        xx1.z = bits2(__floats2bfloat162_rn(v3.x, v3.y));
        xx1.w = bits2(__floats2bfloat162_rn(v3.z, v3.w));
        uint4* dsq = (uint4*)&g_abig[row * 1024 + d];
        uint4* dxx = (uint4*)&g_abig[row * 1024 + 512 + d];
        dsq[0] = sq0;  dsq[1] = sq1;
        dxx[0] = xx0;  dxx[1] = xx1;
    }

    // prepB + ck: 32 units; CTAs 0..31
    if (c < 32) {
        const int e = (c * 256 + tid) * 16;
        const int k = e >> 9;
        const int d = e & 511;
        const float4* sb = (const float4*)(bandwidths + e);
        const float4* sc = (const float4*)(centers + e);
        float4 b0 = sb[0], b1 = sb[1], b2 = sb[2], b3 = sb[3];
        float4 c0 = sc[0], c1 = sc[1], c2 = sc[2], c3 = sc[3];
        uint4 wb0, wb1, wc0, wc1;
        wb0.x = bits2(__floats2bfloat162_rn(b0.x, b0.y));
        wb0.y = bits2(__floats2bfloat162_rn(b0.z, b0.w));
        wb0.z = bits2(__floats2bfloat162_rn(b1.x, b1.y));
        wb0.w = bits2(__floats2bfloat162_rn(b1.z, b1.w));
        wb1.x = bits2(__floats2bfloat162_rn(b2.x, b2.y));
        wb1.y = bits2(__floats2bfloat162_rn(b2.z, b2.w));
        wb1.z = bits2(__floats2bfloat162_rn(b3.x, b3.y));
        wb1.w = bits2(__floats2bfloat162_rn(b3.z, b3.w));
        wc0.x = bits2(__floats2bfloat162_rn(-2.0f * b0.x * c0.x, -2.0f * b0.y * c0.y));
        wc0.y = bits2(__floats2bfloat162_rn(-2.0f * b0.z * c0.z, -2.0f * b0.w * c0.w));
        wc0.z = bits2(__floats2bfloat162_rn(-2.0f * b1.x * c1.x, -2.0f * b1.y * c1.y));
        wc0.w = bits2(__floats2bfloat162_rn(-2.0f * b1.z * c1.z, -2.0f * b1.w * c1.w));
        wc1.x = bits2(__floats2bfloat162_rn(-2.0f * b2.x * c2.x, -2.0f * b2.y * c2.y));
        wc1.y = bits2(__floats2bfloat162_rn(-2.0f * b2.z * c2.z, -2.0f * b2.w * c2.w));
        wc1.z = bits2(__floats2bfloat162_rn(-2.0f * b3.x * c3.x, -2.0f * b3.y * c3.y));
        wc1.w = bits2(__floats2bfloat162_rn(-2.0f * b3.z * c3.z, -2.0f * b3.w * c3.w));
        uint4* db = (uint4*)&g_bmat[k * 1024 + d];
        uint4* dc = (uint4*)&g_bmat[k * 1024 + 512 + d];
        db[0] = wb0;  db[1] = wb1;
        dc[0] = wc0;  dc[1] = wc1;
        float s = b0.x * c0.x * c0.x + b0.y * c0.y * c0.y
                + b0.z * c0.z * c0.z + b0.w * c0.w * c0.w
                + b1.x * c1.x * c1.x + b1.y * c1.y * c1.y
                + b1.z * c1.z * c1.z + b1.w * c1.w * c1.w
                + b2.x * c2.x * c2.x + b2.y * c2.y * c2.y
                + b2.z * c2.z * c2.z + b2.w * c2.w * c2.w
                + b3.x * c3.x * c3.x + b3.y * c3.y * c3.y
                + b3.z * c3.z * c3.z + b3.w * c3.w * c3.w;
        #pragma unroll
        for (int o = 16; o > 0; o >>= 1)
            s += __shfl_down_sync(0xffffffffu, s, o);
        if ((tid & 31) == 0) g_ck[k] = s;
    }

    // prepW: 128 tiles; CTA c does tile c
    {
        const int d0 = (c & 15) * 32, k0 = (c >> 4) * 32;
        const int tx = tid & 31, ty = tid >> 5;          // 32 x 8
        __shared__ float t[32][33];
        #pragma unroll
        for (int jj = 0; jj < 4; jj++) {
            int k = k0 + ty + jj * 8;
            float r = raw[k * Dn + d0 + tx];
            t[ty + jj * 8][tx] = fmaxf(r, 0.0f) + __logf(1.0f + __expf(-fabsf(r)));
        }
        __syncthreads();
        #pragma unroll
        for (int jj = 0; jj < 4; jj++) {
            int d = d0 + ty + jj * 8;
            g_wt[d * Kn + k0 + tx] = __float2bfloat16(t[tx][ty + jj * 8]);
        }
    }

    gridbar(NCTA);                 // prep complete everywhere

    // ================= Phase 1: G1 (dist -> rbf) =================
    gemm_tile<false>(sm, (c & 31) * 64, (c >> 5) * 64, nullptr);

    gridbar(2 * NCTA);             // rbf complete everywhere

    // ================= Phase 2: G2 (h -> out), 2 tiles per CTA =============
    #pragma unroll
    for (int tt = 0; tt < 2; tt++) {
        const int tile = c + tt * NCTA;
        gemm_tile<true>(sm, (tile & 31) * 64, (tile >> 5) * 64, out);
    }

    // ---- barrier state reset for next run/replay -------------------------
    __syncthreads();
    if (tid == 0) {
        unsigned d = atomicAdd(&g_done, 1u);
        if (d == NCTA - 1u) {
            g_count = 0u;
            g_done = 0u;
            __threadfence();
        }
    }
}

// ---------------------------------------------------------------------------
extern "C" void kernel_launch(void* const* d_in, const int* in_sizes, int n_in,
                              void* d_out, int out_size) {
    const float* x           = (const float*)d_in[0];
    const float* centers     = (const float*)d_in[1];
    const float* bandwidths  = (const float*)d_in[2];
    const float* raw_weights = (const float*)d_in[3];
    float* out = (float*)d_out;

    static bool attr_set = false;
    if (!attr_set) {
        cudaFuncSetAttribute(mega_kern,
                             cudaFuncAttributeMaxDynamicSharedMemorySize, SMEMSZ);
        attr_set = true;
    }

    mega_kern<<<NCTA, 256, SMEMSZ>>>(x, centers, bandwidths, raw_weights, out);
}

// round 11
// speedup vs baseline: 1.1235x; 1.1235x over previous
#include <cuda_runtime.h>
#include <cuda_bf16.h>
#include <cstdint>
#include <math.h>

// Problem shape (fixed by setup_inputs)
#define Bn 2048
#define Kn 256
#define Dn 512

// bf16 staging buffers (__device__ globals: allocation-free)
__device__ __nv_bfloat16 g_abig[Bn * 1024];  // [b][ 0..511: x^2 | 512..1023: x ]
__device__ __nv_bfloat16 g_bmat[Kn * 1024];  // [k][ 0..511: bw | 512..1023: -2*bw*c ]
__device__ __nv_bfloat16 g_rbf [Bn * Kn];    // rbf result, K-major for GEMM2
__device__ __nv_bfloat16 g_wt  [Dn * Kn];    // softplus(W) transposed: [d][k]
__device__ float         g_ck  [Kn];         // sum_d bw*c^2

// ---------------------------------------------------------------------------
// Helpers (arch-generic: ldmatrix / mma.sync / cp.async — NO tcgen05, the
// harness PTX stage targets plain compute_103)
// ---------------------------------------------------------------------------
__device__ __forceinline__ uint32_t s2u(const void* p) {
    uint32_t a;
    asm("{ .reg .u64 t; cvta.to.shared.u64 t, %1; cvt.u32.u64 %0, t; }"
        : "=r"(a) : "l"(p));
    return a;
}
#define SW128(o) ((o) ^ (((o) >> 3) & 0x70))

__device__ __forceinline__ void cp16(uint32_t s, const void* g) {
    asm volatile("cp.async.cg.shared.global [%0], [%1], 16;" :: "r"(s), "l"(g));
}

__device__ __forceinline__ void ldsm4(uint32_t* r, uint32_t addr) {
    asm volatile("ldmatrix.sync.aligned.m8n8.x4.shared.b16 {%0,%1,%2,%3}, [%4];"
                 : "=r"(r[0]), "=r"(r[1]), "=r"(r[2]), "=r"(r[3]) : "r"(addr));
}

__device__ __forceinline__ void mma16816(float* c, const uint32_t* a, const uint32_t* b) {
    asm volatile(
        "mma.sync.aligned.m16n8k16.row.col.f32.bf16.bf16.f32 "
        "{%0,%1,%2,%3}, {%4,%5,%6,%7}, {%8,%9}, {%0,%1,%2,%3};"
        : "+f"(c[0]), "+f"(c[1]), "+f"(c[2]), "+f"(c[3])
        : "r"(a[0]), "r"(a[1]), "r"(a[2]), "r"(a[3]), "r"(b[0]), "r"(b[1]));
}

__device__ __forceinline__ uint32_t bits2(__nv_bfloat162 v) {
    return *(uint32_t*)&v;
}

// ---------------------------------------------------------------------------
// Fused prep (R8 known-good): 416 blocks x 256 threads.
//   blocks [0,256):   prepA — 16 elems/thread, 4x LDG.128 -> 4x STG.128
//   blocks [256,288): prepB + ck — 16 elems/thread, one warp per k-row
//   blocks [288,416): prepW — softplus + 32x32 transpose
// ---------------------------------------------------------------------------
__global__ void __launch_bounds__(256)
prep_all(const float* __restrict__ x, const float* __restrict__ centers,
         const float* __restrict__ bandwidths, const float* __restrict__ raw) {
    const int bid = blockIdx.x, tid = threadIdx.x;

    if (bid < 256) {                         // ---- prepA ----
        const int e = (bid * 256 + tid) * 16;
        const int row = e >> 9;
        const int d = e & 511;
        const float4* src = (const float4*)(x + e);
        float4 v0 = src[0], v1 = src[1], v2 = src[2], v3 = src[3];
        uint4 sq0, sq1, xx0, xx1;
        sq0.x = bits2(__floats2bfloat162_rn(v0.x * v0.x, v0.y * v0.y));
        sq0.y = bits2(__floats2bfloat162_rn(v0.z * v0.z, v0.w * v0.w));
        sq0.z = bits2(__floats2bfloat162_rn(v1.x * v1.x, v1.y * v1.y));
        sq0.w = bits2(__floats2bfloat162_rn(v1.z * v1.z, v1.w * v1.w));
        sq1.x = bits2(__floats2bfloat162_rn(v2.x * v2.x, v2.y * v2.y));
        sq1.y = bits2(__floats2bfloat162_rn(v2.z * v2.z, v2.w * v2.w));
        sq1.z = bits2(__floats2bfloat162_rn(v3.x * v3.x, v3.y * v3.y));
        sq1.w = bits2(__floats2bfloat162_rn(v3.z * v3.z, v3.w * v3.w));
        xx0.x = bits2(__floats2bfloat162_rn(v0.x, v0.y));
        xx0.y = bits2(__floats2bfloat162_rn(v0.z, v0.w));
        xx0.z = bits2(__floats2bfloat162_rn(v1.x, v1.y));
        xx0.w = bits2(__floats2bfloat162_rn(v1.z, v1.w));
        xx1.x = bits2(__floats2bfloat162_rn(v2.x, v2.y));
        xx1.y = bits2(__floats2bfloat162_rn(v2.z, v2.w));
        xx1.z = bits2(__floats2bfloat162_rn(v3.x, v3.y));
        xx1.w = bits2(__floats2bfloat162_rn(v3.z, v3.w));
        uint4* dsq = (uint4*)&g_abig[row * 1024 + d];
        uint4* dxx = (uint4*)&g_abig[row * 1024 + 512 + d];
        dsq[0] = sq0;  dsq[1] = sq1;
        dxx[0] = xx0;  dxx[1] = xx1;
        return;
    }

    if (bid < 288) {                         // ---- prepB + ck ----
        const int e = ((bid - 256) * 256 + tid) * 16;
        const int k = e >> 9;
        const int d = e & 511;
        const float4* sb = (const float4*)(bandwidths + e);
        const float4* sc = (const float4*)(centers + e);
        float4 b0 = sb[0], b1 = sb[1], b2 = sb[2], b3 = sb[3];
        float4 c0 = sc[0], c1 = sc[1], c2 = sc[2], c3 = sc[3];
        uint4 wb0, wb1, wc0, wc1;
        wb0.x = bits2(__floats2bfloat162_rn(b0.x, b0.y));
        wb0.y = bits2(__floats2bfloat162_rn(b0.z, b0.w));
        wb0.z = bits2(__floats2bfloat162_rn(b1.x, b1.y));
        wb0.w = bits2(__floats2bfloat162_rn(b1.z, b1.w));
        wb1.x = bits2(__floats2bfloat162_rn(b2.x, b2.y));
        wb1.y = bits2(__floats2bfloat162_rn(b2.z, b2.w));
        wb1.z = bits2(__floats2bfloat162_rn(b3.x, b3.y));
        wb1.w = bits2(__floats2bfloat162_rn(b3.z, b3.w));
        wc0.x = bits2(__floats2bfloat162_rn(-2.0f * b0.x * c0.x, -2.0f * b0.y * c0.y));
        wc0.y = bits2(__floats2bfloat162_rn(-2.0f * b0.z * c0.z, -2.0f * b0.w * c0.w));
        wc0.z = bits2(__floats2bfloat162_rn(-2.0f * b1.x * c1.x, -2.0f * b1.y * c1.y));
        wc0.w = bits2(__floats2bfloat162_rn(-2.0f * b1.z * c1.z, -2.0f * b1.w * c1.w));
        wc1.x = bits2(__floats2bfloat162_rn(-2.0f * b2.x * c2.x, -2.0f * b2.y * c2.y));
        wc1.y = bits2(__floats2bfloat162_rn(-2.0f * b2.z * c2.z, -2.0f * b2.w * c2.w));
        wc1.z = bits2(__floats2bfloat162_rn(-2.0f * b3.x * c3.x, -2.0f * b3.y * c3.y));
        wc1.w = bits2(__floats2bfloat162_rn(-2.0f * b3.z * c3.z, -2.0f * b3.w * c3.w));
        uint4* db = (uint4*)&g_bmat[k * 1024 + d];
        uint4* dc = (uint4*)&g_bmat[k * 1024 + 512 + d];
        db[0] = wb0;  db[1] = wb1;
        dc[0] = wc0;  dc[1] = wc1;
        float s = b0.x * c0.x * c0.x + b0.y * c0.y * c0.y
                + b0.z * c0.z * c0.z + b0.w * c0.w * c0.w
                + b1.x * c1.x * c1.x + b1.y * c1.y * c1.y
                + b1.z * c1.z * c1.z + b1.w * c1.w * c1.w
                + b2.x * c2.x * c2.x + b2.y * c2.y * c2.y
                + b2.z * c2.z * c2.z + b2.w * c2.w * c2.w
                + b3.x * c3.x * c3.x + b3.y * c3.y * c3.y
                + b3.z * c3.z * c3.z + b3.w * c3.w * c3.w;
        #pragma unroll
        for (int o = 16; o > 0; o >>= 1)
            s += __shfl_down_sync(0xffffffffu, s, o);
        if ((tid & 31) == 0) g_ck[k] = s;
        return;
    }

    {                                        // ---- prepW ----
        const int t2 = bid - 288;
        const int d0 = (t2 & 15) * 32, k0 = (t2 >> 4) * 32;
        const int tx = tid & 31, ty = tid >> 5;          // 32 x 8
        __shared__ float t[32][33];
        #pragma unroll
        for (int jj = 0; jj < 4; jj++) {
            int k = k0 + ty + jj * 8;
            float r = raw[k * Dn + d0 + tx];
            t[ty + jj * 8][tx] = fmaxf(r, 0.0f) + __logf(1.0f + __expf(-fabsf(r)));
        }
        __syncthreads();
        #pragma unroll
        for (int jj = 0; jj < 4; jj++) {
            int d = d0 + ty + jj * 8;
            g_wt[d * Kn + k0 + tx] = __float2bfloat16(t[tx][ty + jj * 8]);
        }
    }
}

// ---------------------------------------------------------------------------
// HMMA bf16 GEMM, split-K across two warp groups, REGISTER-PIPELINED
// fragments (prefetch ks+1 ldsm before ks MMAs — breaks ldsm->mma dependency).
//   G1 (ISG2=false): 6 stages / 96KB, 16 chunks, exp -> bf16 g_rbf
//   G2 (ISG2=true):  4 stages / 64KB (2 CTAs/SM), 4 chunks all loaded upfront,
//                    1/(h+eps) -> out
// ---------------------------------------------------------------------------
#define STAGE_BYTES 16384
#define G1_NST 6
#define G2_NST 4
#define G1_SMEM (G1_NST * STAGE_BYTES)   // 98304
#define G2_SMEM (G2_NST * STAGE_BYTES)   // 65536

template<bool ISG2>
__global__ void __launch_bounds__(256)
gemm_kern(float* __restrict__ out) {
    constexpr int LD     = ISG2 ? 256 : 1024;
    constexpr int NCHUNK = ISG2 ? 4   : 16;
    constexpr int NSTEP  = NCHUNK / 2;
    constexpr int NST    = ISG2 ? G2_NST : G1_NST;
    const __nv_bfloat16* __restrict__ A  = ISG2 ? g_rbf : g_abig;
    const __nv_bfloat16* __restrict__ Bm = ISG2 ? g_wt  : g_bmat;

    extern __shared__ char sm[];
    const uint32_t T0 = s2u(sm);
    const int tid = threadIdx.x, wid = tid >> 5, l = tid & 31;
    const int m0 = blockIdx.x * 64, n0 = blockIdx.y * 64;
    const int grp = wid >> 2, wg = wid & 3;
    const int wm = wg & 1, wn = wg >> 1;

    const int lr = l & 7, sel = l >> 3;
    const int a_row = wm * 32 + (sel & 1) * 8 + lr;
    const uint32_t a_kb = (uint32_t)((sel >> 1) * 16);
    const int b_row = wn * 32 + (sel >> 1) * 8 + lr;
    const uint32_t b_kb = (uint32_t)((sel & 1) * 16);

    #define LOAD_CHUNK(ch) do {                                              \
        uint32_t _sa = T0 + ((ch) % NST) * STAGE_BYTES;                      \
        const __nv_bfloat16* _ga = A  + (size_t)m0 * LD + (ch) * 64;         \
        const __nv_bfloat16* _gb = Bm + (size_t)n0 * LD + (ch) * 64;         \
        _Pragma("unroll")                                                    \
        for (int q = 0; q < 2; q++) {                                        \
            int u = tid + q * 256;                                           \
            int r = u >> 3, cc = u & 7;                                      \
            uint32_t off = SW128((uint32_t)(r * 128 + cc * 16));             \
            cp16(_sa        + off, _ga + (size_t)r * LD + cc * 8);           \
            cp16(_sa + 8192 + off, _gb + (size_t)r * LD + cc * 8);           \
        }                                                                    \
    } while (0)

    #define LOAD_PAIR(p) do {                                                \
        LOAD_CHUNK(2 * (p));  LOAD_CHUNK(2 * (p) + 1);                       \
        asm volatile("cp.async.commit_group;");                              \
    } while (0)

    // fragment fetch for step ks into register buffer buf
    #define LDFRAG(sa, sbb, ks, buf) do {                                    \
        _Pragma("unroll")                                                    \
        for (int mi = 0; mi < 2; mi++)                                       \
            ldsm4(af[buf][mi], (sa) + SW128((uint32_t)((a_row + mi * 16) * 128) \
                                            + (uint32_t)((ks) * 32) + a_kb)); \
        _Pragma("unroll")                                                    \
        for (int bi = 0; bi < 2; bi++)                                       \
            ldsm4(bf[buf][bi], (sbb) + SW128((uint32_t)((b_row + bi * 16) * 128) \
                                             + (uint32_t)((ks) * 32) + b_kb)); \
    } while (0)

    float acc[2][4][4];
    #pragma unroll
    for (int mi = 0; mi < 2; mi++)
        #pragma unroll
        for (int nj = 0; nj < 4; nj++)
            #pragma unroll
            for (int e = 0; e < 4; e++) acc[mi][nj][e] = 0.0f;

    LOAD_PAIR(0);
    if (NSTEP > 1) LOAD_PAIR(1);

    uint32_t af[2][2][4], bf[2][2][4];

    for (int t = 0; t < NSTEP; t++) {
        if (t < NSTEP - 1) asm volatile("cp.async.wait_group 1;");
        else               asm volatile("cp.async.wait_group 0;");
        __syncthreads();
        if (t + 2 < NSTEP) LOAD_PAIR(t + 2);

        const int ch = 2 * t + grp;
        const uint32_t sa  = T0 + (ch % NST) * STAGE_BYTES;
        const uint32_t sbb = sa + 8192;

        LDFRAG(sa, sbb, 0, 0);                      // preload ks=0
        #pragma unroll
        for (int ks = 0; ks < 4; ks++) {
            const int cur = ks & 1;
            if (ks < 3) LDFRAG(sa, sbb, ks + 1, cur ^ 1);   // prefetch ks+1
            #pragma unroll
            for (int mi = 0; mi < 2; mi++)
                #pragma unroll
                for (int nj = 0; nj < 4; nj++)
                    mma16816(acc[mi][nj], af[cur][mi], &bf[cur][nj >> 1][(nj & 1) * 2]);
        }
    }
    #undef LDFRAG
    #undef LOAD_PAIR
    #undef LOAD_CHUNK

    // ---- cross-group reduce through smem (pitch 72 floats) ---------------
    float* Rb = (float*)sm;
    const int rrow = wm * 32 + (l >> 2);
    const int rcol = wn * 32 + 2 * (l & 3);
    __syncthreads();
    if (grp == 1) {
        #pragma unroll
        for (int mi = 0; mi < 2; mi++)
            #pragma unroll
            for (int nj = 0; nj < 4; nj++) {
                const int r = rrow + mi * 16, c = rcol + nj * 8;
                *(float2*)&Rb[r * 72 + c]       = make_float2(acc[mi][nj][0], acc[mi][nj][1]);
                *(float2*)&Rb[(r + 8) * 72 + c] = make_float2(acc[mi][nj][2], acc[mi][nj][3]);
            }
    }
    __syncthreads();
    if (grp == 1) return;

    #pragma unroll
    for (int mi = 0; mi < 2; mi++)
        #pragma unroll
        for (int nj = 0; nj < 4; nj++) {
            const int r = rrow + mi * 16, c = rcol + nj * 8;
            float2 p0 = *(const float2*)&Rb[r * 72 + c];
            float2 p1 = *(const float2*)&Rb[(r + 8) * 72 + c];
            acc[mi][nj][0] += p0.x;  acc[mi][nj][1] += p0.y;
            acc[mi][nj][2] += p1.x;  acc[mi][nj][3] += p1.y;
        }

    // ---- Epilogue (group 0 only) -----------------------------------------
    const int erow = m0 + rrow;

    if (!ISG2) {
        #pragma unroll
        for (int mi = 0; mi < 2; mi++) {
            #pragma unroll
            for (int nj = 0; nj < 4; nj++) {
                const int col = rcol + nj * 8;
                const float ck0 = g_ck[n0 + col];
                const float ck1 = g_ck[n0 + col + 1];
                const int r = erow + mi * 16;
                float v0 = __expf(-0.5f * (acc[mi][nj][0] + ck0));
                float v1 = __expf(-0.5f * (acc[mi][nj][1] + ck1));
                float v2 = __expf(-0.5f * (acc[mi][nj][2] + ck0));
                float v3 = __expf(-0.5f * (acc[mi][nj][3] + ck1));
                __nv_bfloat162 p0 = __floats2bfloat162_rn(v0, v1);
                __nv_bfloat162 p1 = __floats2bfloat162_rn(v2, v3);
                *(__nv_bfloat162*)&g_rbf[(size_t)r * Kn + n0 + col]       = p0;
                *(__nv_bfloat162*)&g_rbf[(size_t)(r + 8) * Kn + n0 + col] = p1;
            }
        }
    } else {
        const float eps = 1e-3f;
        #pragma unroll
        for (int mi = 0; mi < 2; mi++) {
            #pragma unroll
            for (int nj = 0; nj < 4; nj++) {
                const int col = n0 + rcol + nj * 8;
                const int r = erow + mi * 16;
                float2 o0, o1;
                o0.x = __fdividef(1.0f, acc[mi][nj][0] + eps);
                o0.y = __fdividef(1.0f, acc[mi][nj][1] + eps);
                o1.x = __fdividef(1.0f, acc[mi][nj][2] + eps);
                o1.y = __fdividef(1.0f, acc[mi][nj][3] + eps);
                *(float2*)(out + (size_t)r * Dn + col)       = o0;
                *(float2*)(out + (size_t)(r + 8) * Dn + col) = o1;
            }
        }
    }
}

// ---------------------------------------------------------------------------
extern "C" void kernel_launch(void* const* d_in, const int* in_sizes, int n_in,
                              void* d_out, int out_size) {
    const float* x           = (const float*)d_in[0];
    const float* centers     = (const float*)d_in[1];
    const float* bandwidths  = (const float*)d_in[2];
    const float* raw_weights = (const float*)d_in[3];
    float* out = (float*)d_out;

    static bool attr_set = false;
    if (!attr_set) {
        cudaFuncSetAttribute(gemm_kern<false>,
                             cudaFuncAttributeMaxDynamicSharedMemorySize, G1_SMEM);
        cudaFuncSetAttribute(gemm_kern<true>,
                             cudaFuncAttributeMaxDynamicSharedMemorySize, G2_SMEM);
        attr_set = true;
    }

    prep_all<<<416, 256>>>(x, centers, bandwidths, raw_weights);

    // G1: dist GEMM (M=2048, N=256, K=1024) -> rbf (bf16)
    gemm_kern<false><<<dim3(Bn / 64, Kn / 64), 256, G1_SMEM>>>(nullptr);
    // G2: h GEMM (M=2048, N=512, K=256) -> out = 1/(h+eps), 2 CTAs/SM
    gemm_kern<true><<<dim3(Bn / 64, Dn / 64), 256, G2_SMEM>>>(out);
}